// round 6
// baseline (speedup 1.0000x reference)
#include <cuda_runtime.h>
#include <cstddef>
#include <cstdint>

#define T_   512
#define B_   64
#define E_   300
#define H_   512
#define L_   5
#define G3H_ 1536
#define NBLK 128
#define NTHR 256

typedef unsigned long long ull;

// ---------------- scratch (no allocations allowed) ----------------
__device__ float g_xp0[(size_t)T_ * B_ * G3H_];   // 201 MB
__device__ float g_xp1[(size_t)T_ * B_ * G3H_];   // 201 MB
__device__ float g_h1 [(size_t)T_ * B_ * H_];     // 67 MB  (layer0 history, [t*B+b][H])
__device__ float g_hT [2 * H_ * B_];              // h double buffer, [buf][k][b]
__device__ float g_pooled[T_ * H_];
__device__ unsigned int g_arrive;

__global__ void init_kernel() { g_arrive = 0u; }

// ---------------- f32x2 helpers (FFMA2 only reachable via PTX) ----------------
__device__ __forceinline__ ull ffma2(ull a, ull b, ull c) {
    ull d;
    asm("fma.rn.f32x2 %0, %1, %2, %3;" : "=l"(d) : "l"(a), "l"(b), "l"(c));
    return d;
}
__device__ __forceinline__ ull pack2(float lo, float hi) {
    ull d;
    asm("mov.b64 %0, {%1, %2};" : "=l"(d) : "f"(lo), "f"(hi));
    return d;
}
__device__ __forceinline__ float2 unpack2(ull v) {
    float2 r;
    asm("mov.b64 {%0, %1}, %2;" : "=f"(r.x), "=f"(r.y) : "l"(v));
    return r;
}
__device__ __forceinline__ uint32_t smem_u32(const void* p) {
    uint32_t a;
    asm("{ .reg .u64 t; cvta.to.shared.u64 t, %1; cvt.u32.u64 %0, t; }" : "=r"(a) : "l"(p));
    return a;
}
__device__ __forceinline__ void cp_async16(uint32_t dst, const void* src) {
    asm volatile("cp.async.cg.shared.global [%0], [%1], 16;" :: "r"(dst), "l"(src));
}

// ---------------- grid-wide barrier (all 128 CTAs co-resident, 1 CTA/SM) ----------------
__device__ __forceinline__ void grid_barrier(unsigned int* epoch) {
    __syncthreads();
    if (threadIdx.x == 0) {
        __threadfence();
        unsigned int target = (*epoch + 1u) * NBLK;
        atomicAdd(&g_arrive, 1u);
        while (*((volatile unsigned int*)&g_arrive) < target) { }
        __threadfence();
    }
    __syncthreads();
    ++(*epoch);
}

// ---------------- fp32 GEMM: C[M,N] = A[M,K] @ W[N,K]^T + bias ----------------
// 128x128x16 tile, 8x8 per thread, f32x2 inner with DUPLICATED W pairs in smem
// (pack-free inner loop: 32 FFMA2 + 8 LDS per kk). Register-prefetch next tile.
__global__ void __launch_bounds__(256) gemm_kernel(
    const float* __restrict__ A, const int* __restrict__ gather,
    const float* __restrict__ W, const float* __restrict__ bias,
    float* __restrict__ C, int M, int N, int K)
{
    __shared__ __align__(16) float As[16][132];
    __shared__ __align__(16) float Wd[16][264];   // [kk][2n..2n+1] duplicated

    const int tid = threadIdx.x;
    const int tx = tid & 15;          // n-tile (8 cols)
    const int ty = tid >> 4;          // m-tile (8 rows)
    const int m0 = blockIdx.y * 128;
    const int n0 = blockIdx.x * 128;

    // staging ids: row sr (0..63, x2), k-quad sq
    const int sr = tid >> 2;
    const int sq = tid & 3;

    // precompute gathered/plain row bases
    const float* arow[2];
    const float* wrow[2];
    #pragma unroll
    for (int r = 0; r < 2; ++r) {
        int am = m0 + sr + 64 * r;
        if (gather) am = gather[am];
        arow[r] = A + (size_t)am * K;
        wrow[r] = W + (size_t)(n0 + sr + 64 * r) * K;
    }

    ull acc[4][8];
    #pragma unroll
    for (int mp = 0; mp < 4; ++mp)
        #pragma unroll
        for (int n = 0; n < 8; ++n) acc[mp][n] = 0ull;

    const int Kiter = (K + 15) >> 4;

    float4 pa[2], pw[2];
    // prefetch k0 = 0
    {
        int k = sq * 4;
        #pragma unroll
        for (int r = 0; r < 2; ++r) {
            if (k + 3 < K) {
                pa[r] = *(const float4*)(arow[r] + k);
                pw[r] = *(const float4*)(wrow[r] + k);
            } else {
                float4 za = {0.f,0.f,0.f,0.f}, zw = {0.f,0.f,0.f,0.f};
                #pragma unroll
                for (int j = 0; j < 4; ++j) {
                    if (k + j < K) {
                        ((float*)&za)[j] = arow[r][k + j];
                        ((float*)&zw)[j] = wrow[r][k + j];
                    }
                }
                pa[r] = za; pw[r] = zw;
            }
        }
    }

    for (int ki = 0; ki < Kiter; ++ki) {
        // ---- store staged tile ----
        #pragma unroll
        for (int r = 0; r < 2; ++r) {
            int mm = sr + 64 * r;
            As[sq * 4 + 0][mm] = pa[r].x;
            As[sq * 4 + 1][mm] = pa[r].y;
            As[sq * 4 + 2][mm] = pa[r].z;
            As[sq * 4 + 3][mm] = pa[r].w;
            *(ull*)&Wd[sq * 4 + 0][2 * mm] = pack2(pw[r].x, pw[r].x);
            *(ull*)&Wd[sq * 4 + 1][2 * mm] = pack2(pw[r].y, pw[r].y);
            *(ull*)&Wd[sq * 4 + 2][2 * mm] = pack2(pw[r].z, pw[r].z);
            *(ull*)&Wd[sq * 4 + 3][2 * mm] = pack2(pw[r].w, pw[r].w);
        }
        __syncthreads();

        // ---- prefetch next tile ----
        if (ki + 1 < Kiter) {
            int k = (ki + 1) * 16 + sq * 4;
            #pragma unroll
            for (int r = 0; r < 2; ++r) {
                if (k + 3 < K) {
                    pa[r] = *(const float4*)(arow[r] + k);
                    pw[r] = *(const float4*)(wrow[r] + k);
                } else {
                    float4 za = {0.f,0.f,0.f,0.f}, zw = {0.f,0.f,0.f,0.f};
                    #pragma unroll
                    for (int j = 0; j < 4; ++j) {
                        if (k + j < K) {
                            ((float*)&za)[j] = arow[r][k + j];
                            ((float*)&zw)[j] = wrow[r][k + j];
                        }
                    }
                    pa[r] = za; pw[r] = zw;
                }
            }
        }

        // ---- compute ----
        #pragma unroll
        for (int kk = 0; kk < 16; ++kk) {
            ull a[4];
            a[0] = *(const ull*)&As[kk][ty * 8 + 0];
            a[1] = *(const ull*)&As[kk][ty * 8 + 2];
            a[2] = *(const ull*)&As[kk][ty * 8 + 4];
            a[3] = *(const ull*)&As[kk][ty * 8 + 6];
            ulonglong2 w01 = *(const ulonglong2*)&Wd[kk][tx * 16 + 0];
            ulonglong2 w23 = *(const ulonglong2*)&Wd[kk][tx * 16 + 4];
            ulonglong2 w45 = *(const ulonglong2*)&Wd[kk][tx * 16 + 8];
            ulonglong2 w67 = *(const ulonglong2*)&Wd[kk][tx * 16 + 12];
            ull w[8] = {w01.x, w01.y, w23.x, w23.y, w45.x, w45.y, w67.x, w67.y};
            #pragma unroll
            for (int mp = 0; mp < 4; ++mp)
                #pragma unroll
                for (int n = 0; n < 8; ++n)
                    acc[mp][n] = ffma2(a[mp], w[n], acc[mp][n]);
        }
        __syncthreads();
    }

    // ---- epilogue ----
    float bs[8];
    #pragma unroll
    for (int n = 0; n < 8; ++n) bs[n] = bias[n0 + tx * 8 + n];

    #pragma unroll
    for (int mp = 0; mp < 4; ++mp) {
        float2 v[8];
        #pragma unroll
        for (int n = 0; n < 8; ++n) v[n] = unpack2(acc[mp][n]);
        size_t r0 = (size_t)(m0 + ty * 8 + mp * 2 + 0) * N + n0 + tx * 8;
        size_t r1 = (size_t)(m0 + ty * 8 + mp * 2 + 1) * N + n0 + tx * 8;
        float4 o;
        o.x = v[0].x + bs[0]; o.y = v[1].x + bs[1]; o.z = v[2].x + bs[2]; o.w = v[3].x + bs[3];
        *(float4*)&C[r0 + 0] = o;
        o.x = v[4].x + bs[4]; o.y = v[5].x + bs[5]; o.z = v[6].x + bs[6]; o.w = v[7].x + bs[7];
        *(float4*)&C[r0 + 4] = o;
        o.x = v[0].y + bs[0]; o.y = v[1].y + bs[1]; o.z = v[2].y + bs[2]; o.w = v[3].y + bs[3];
        *(float4*)&C[r1 + 0] = o;
        o.x = v[4].y + bs[4]; o.y = v[5].y + bs[5]; o.z = v[6].y + bs[6]; o.w = v[7].y + bs[7];
        *(float4*)&C[r1 + 4] = o;
    }
}

// ---------------- persistent GRU recurrence (f32x2, cp.async, 2x256k chunks) ----------------
#define RS_WT    0
#define RS_HT    (512 * 20 * 4)                    // 40960
#define RS_RED   (RS_HT + 2 * 256 * 64 * 4)        // 40960 + 131072 = 172032
#define RS_XPS   (RS_RED + 32 * 8 * 12 * 8)        // + 24576 = 196608
#define RS_POOL  (RS_XPS + 192 * 16)               // + 3072 = 199680
#define RS_TOTAL (RS_POOL + 1024)                  // 200704

__global__ void __launch_bounds__(256) recur_kernel(
    const float* __restrict__ xp, const float* __restrict__ Whh,
    const float* __restrict__ bhh, float* __restrict__ hT,
    float* __restrict__ hist, float* __restrict__ pooled)
{
    extern __shared__ char smem_raw[];
    float* wt   = (float*)(smem_raw + RS_WT);      // [k][20]
    float* h_ts = (float*)(smem_raw + RS_HT);      // [2][256][64]
    ull*   red  = (ull*)  (smem_raw + RS_RED);     // [pos32][ks8][12]
    float* xps  = (float*)(smem_raw + RS_XPS);     // [3][64] float4
    float* pool = (float*)(smem_raw + RS_POOL);    // [4][64]

    const int tid = threadIdx.x;
    const int u0  = blockIdx.x * 4;

    for (int n = 0; n < 12; ++n) {
        int g = n >> 2, jj = n & 3;
        int posn = n + ((n >= 6) ? 2 : 0);
        const float* row = Whh + (size_t)(g * 512 + u0 + jj) * 512;
        for (int k = tid; k < 512; k += 256) wt[k * 20 + posn] = row[k];
    }

    const int b  = tid & 63;
    const int jj = tid >> 6;
    const float bh0 = bhh[u0 + jj];
    const float bh1 = bhh[512 + u0 + jj];
    const float bh2 = bhh[1024 + u0 + jj];

    const int lane = tid & 31;
    const int warp = tid >> 5;
    const int mg   = lane & 15;
    const int ng   = lane >> 4;

    const uint32_t hts_base = smem_u32(h_ts);
    __syncthreads();

    unsigned int epoch = 0;

    for (int t = 0; t < T_; ++t) {
        if (tid < 192) {
            int bb = tid & 63, g = tid >> 6;
            *(float4*)&xps[(g * 64 + bb) * 4] =
                *(const float4*)(xp + ((size_t)t * 64 + bb) * G3H_ + g * 512 + u0);
        }

        ull acc[4][3];
        #pragma unroll
        for (int m = 0; m < 4; ++m)
            #pragma unroll
            for (int np = 0; np < 3; ++np) acc[m][np] = 0ull;

        const float* hp = hT + (size_t)((t - 1) & 1) * 512 * 64;

        if (t > 0) {
            // issue both 64KB chunk loads up-front (streams under compute)
            #pragma unroll
            for (int c = 0; c < 2; ++c) {
                uint32_t dst = hts_base + c * 65536;
                const float* src = hp + c * 16384;
                #pragma unroll
                for (int q = 0; q < 16; ++q) {
                    int idx = tid + q * 256;
                    cp_async16(dst + idx * 16, src + idx * 4);
                }
                asm volatile("cp.async.commit_group;" ::: "memory");
            }
            #pragma unroll 1
            for (int c = 0; c < 2; ++c) {
                if (c == 0) asm volatile("cp.async.wait_group 1;" ::: "memory");
                else        asm volatile("cp.async.wait_group 0;" ::: "memory");
                __syncthreads();

                const float* hb = h_ts + c * 16384;
                #pragma unroll
                for (int i = 0; i < 32; ++i) {
                    int kk = warp * 32 + i;            // 0..255 within chunk
                    int k  = c * 256 + kk;
                    float4 h4 = *(const float4*)&hb[kk * 64 + mg * 4];
                    const float* wr = &wt[k * 20 + ng * 8];
                    ull wp0 = *(const ull*)(wr + 0);
                    ull wp1 = *(const ull*)(wr + 2);
                    ull wp2 = *(const ull*)(wr + 4);
                    ull hd;
                    hd = pack2(h4.x, h4.x);
                    acc[0][0] = ffma2(hd, wp0, acc[0][0]);
                    acc[0][1] = ffma2(hd, wp1, acc[0][1]);
                    acc[0][2] = ffma2(hd, wp2, acc[0][2]);
                    hd = pack2(h4.y, h4.y);
                    acc[1][0] = ffma2(hd, wp0, acc[1][0]);
                    acc[1][1] = ffma2(hd, wp1, acc[1][1]);
                    acc[1][2] = ffma2(hd, wp2, acc[1][2]);
                    hd = pack2(h4.z, h4.z);
                    acc[2][0] = ffma2(hd, wp0, acc[2][0]);
                    acc[2][1] = ffma2(hd, wp1, acc[2][1]);
                    acc[2][2] = ffma2(hd, wp2, acc[2][2]);
                    hd = pack2(h4.w, h4.w);
                    acc[3][0] = ffma2(hd, wp0, acc[3][0]);
                    acc[3][1] = ffma2(hd, wp1, acc[3][1]);
                    acc[3][2] = ffma2(hd, wp2, acc[3][2]);
                }
            }
        }

        __syncthreads();
        {
            int pos = mg * 2 + ng;
            ull* rp = &red[(pos * 8 + warp) * 12];
            #pragma unroll
            for (int m = 0; m < 4; ++m)
                #pragma unroll
                for (int np = 0; np < 3; ++np) rp[m * 3 + np] = acc[m][np];
        }
        __syncthreads();

        const float* redf = (const float*)red;
        float gh[3];
        #pragma unroll
        for (int g = 0; g < 3; ++g) {
            int n   = g * 4 + jj;
            int ngE = (n >= 6);
            int idx = n - ngE * 6;
            int npE = idx >> 1, half = idx & 1;
            int posE = (b >> 2) * 2 + ngE;
            int mE   = b & 3;
            int base = ((posE * 8) * 12 + mE * 3 + npE) * 2 + half;
            float s = 0.f;
            #pragma unroll
            for (int ks = 0; ks < 8; ++ks) s += redf[base + ks * 24];
            gh[g] = s;
        }

        float xr = xps[(0 * 64 + b) * 4 + jj];
        float xz = xps[(1 * 64 + b) * 4 + jj];
        float xn = xps[(2 * 64 + b) * 4 + jj];
        float hprev = (t > 0) ? __ldcg(&hp[(u0 + jj) * 64 + b]) : 0.f;

        float r = 1.f / (1.f + __expf(-(xr + gh[0] + bh0)));
        float z = 1.f / (1.f + __expf(-(xz + gh[1] + bh1)));
        float nn = tanhf(xn + r * (gh[2] + bh2));
        float hnew = (1.f - z) * nn + z * hprev;

        hT[(size_t)(t & 1) * 512 * 64 + (u0 + jj) * 64 + b] = hnew;
        if (hist) hist[((size_t)t * 64 + b) * 512 + u0 + jj] = hnew;

        if (pooled) {
            pool[jj * 64 + b] = hnew;
            __syncthreads();
            if (tid < 4) {
                float s = 0.f;
                #pragma unroll 8
                for (int q = 0; q < 64; ++q) s += pool[tid * 64 + q];
                pooled[t * 512 + u0 + tid] = s * (1.0f / 64.0f);
            }
        }

        if (t < T_ - 1) grid_barrier(&epoch);
    }
}

// ---------------- final FC ----------------
__global__ void fc_kernel(const float* __restrict__ pooled, const float* __restrict__ fcW,
                          const float* __restrict__ fcb, float* __restrict__ out)
{
    int t    = blockIdx.x;
    int lane = threadIdx.x;
    float acc[L_];
    #pragma unroll
    for (int l = 0; l < L_; ++l) acc[l] = 0.f;
    for (int k = lane; k < 512; k += 32) {
        float p = pooled[t * 512 + k];
        #pragma unroll
        for (int l = 0; l < L_; ++l) acc[l] = fmaf(p, fcW[l * 512 + k], acc[l]);
    }
    #pragma unroll
    for (int l = 0; l < L_; ++l) {
        #pragma unroll
        for (int off = 16; off > 0; off >>= 1)
            acc[l] += __shfl_down_sync(0xffffffffu, acc[l], off);
    }
    if (lane == 0) {
        #pragma unroll
        for (int l = 0; l < L_; ++l) out[t * L_ + l] = acc[l] + fcb[l];
    }
}

// ---------------- launch ----------------
extern "C" void kernel_launch(void* const* d_in, const int* in_sizes, int n_in,
                              void* d_out, int out_size)
{
    const int*   texts = (const int*)  d_in[0];
    const float* emb   = (const float*)d_in[1];
    const float* Wih0  = (const float*)d_in[2];
    const float* Whh0  = (const float*)d_in[3];
    const float* bih0  = (const float*)d_in[4];
    const float* bhh0  = (const float*)d_in[5];
    const float* Wih1  = (const float*)d_in[6];
    const float* Whh1  = (const float*)d_in[7];
    const float* bih1  = (const float*)d_in[8];
    const float* bhh1  = (const float*)d_in[9];
    const float* fcW   = (const float*)d_in[10];
    const float* fcb   = (const float*)d_in[11];
    float* out = (float*)d_out;

    float *xp0, *xp1, *h1, *hT, *pooled;
    cudaGetSymbolAddress((void**)&xp0,    g_xp0);
    cudaGetSymbolAddress((void**)&xp1,    g_xp1);
    cudaGetSymbolAddress((void**)&h1,     g_h1);
    cudaGetSymbolAddress((void**)&hT,     g_hT);
    cudaGetSymbolAddress((void**)&pooled, g_pooled);

    static bool attr_set = false;
    if (!attr_set) {
        cudaFuncSetAttribute(recur_kernel,
                             cudaFuncAttributeMaxDynamicSharedMemorySize, RS_TOTAL);
        attr_set = true;
    }

    const int M = T_ * B_;                  // 32768
    dim3 ggrid(G3H_ / 128, M / 128);        // (12, 256)

    // layer 0 input projection (embedding gather fused)
    gemm_kernel<<<ggrid, 256>>>(emb, texts, Wih0, bih0, xp0, M, G3H_, E_);

    // layer 0 recurrence -> h1 history ([t*B+b][H] for the next GEMM)
    init_kernel<<<1, 1>>>();
    recur_kernel<<<NBLK, NTHR, RS_TOTAL>>>(xp0, Whh0, bhh0, hT, h1, nullptr);

    // layer 1 input projection
    gemm_kernel<<<ggrid, 256>>>(h1, nullptr, Wih1, bih1, xp1, M, G3H_, H_);

    // layer 1 recurrence + batch-mean pooling
    init_kernel<<<1, 1>>>();
    recur_kernel<<<NBLK, NTHR, RS_TOTAL>>>(xp1, Whh1, bhh1, hT, nullptr, pooled);

    // final projection
    fc_kernel<<<T_, 32>>>(pooled, fcW, fcb, out);
}

// round 7
// speedup vs baseline: 1.3966x; 1.3966x over previous
#include <cuda_runtime.h>
#include <cstddef>
#include <cstdint>

#define T_   512
#define B_   64
#define E_   300
#define H_   512
#define L_   5
#define G3H_ 1536
#define NBLK 128
#define NTHR 256

typedef unsigned long long ull;

// ---------------- scratch (no allocations allowed) ----------------
__device__ float g_xp0[(size_t)T_ * B_ * G3H_];   // 201 MB
__device__ float g_xp1[(size_t)T_ * B_ * G3H_];   // 201 MB
__device__ float g_h1 [(size_t)T_ * B_ * H_];     // 67 MB  (layer0 history, [t*B+b][H])
__device__ float g_hT [2 * H_ * B_];              // h double buffer, [buf][k][b]
__device__ float g_pooled[T_ * H_];
__device__ unsigned int g_arrive;

__global__ void init_kernel() { g_arrive = 0u; }

// ---------------- f32x2 helpers (FFMA2 only reachable via PTX) ----------------
__device__ __forceinline__ ull ffma2(ull a, ull b, ull c) {
    ull d;
    asm("fma.rn.f32x2 %0, %1, %2, %3;" : "=l"(d) : "l"(a), "l"(b), "l"(c));
    return d;
}
__device__ __forceinline__ ull pack2(float lo, float hi) {
    ull d;
    asm("mov.b64 %0, {%1, %2};" : "=l"(d) : "f"(lo), "f"(hi));
    return d;
}
__device__ __forceinline__ float2 unpack2(ull v) {
    float2 r;
    asm("mov.b64 {%0, %1}, %2;" : "=f"(r.x), "=f"(r.y) : "l"(v));
    return r;
}
__device__ __forceinline__ uint32_t smem_u32(const void* p) {
    uint32_t a;
    asm("{ .reg .u64 t; cvta.to.shared.u64 t, %1; cvt.u32.u64 %0, t; }" : "=r"(a) : "l"(p));
    return a;
}
__device__ __forceinline__ void cp_async16(uint32_t dst, const void* src) {
    asm volatile("cp.async.cg.shared.global [%0], [%1], 16;" :: "r"(dst), "l"(src));
}

// ---------------- grid-wide barrier (all 128 CTAs co-resident, 1 CTA/SM) ----------------
__device__ __forceinline__ void grid_barrier(unsigned int* epoch) {
    __syncthreads();
    if (threadIdx.x == 0) {
        __threadfence();
        unsigned int target = (*epoch + 1u) * NBLK;
        atomicAdd(&g_arrive, 1u);
        while (*((volatile unsigned int*)&g_arrive) < target) { }
        __threadfence();
    }
    __syncthreads();
    ++(*epoch);
}

// ---------------- fp32 GEMM: C[M,N] = A[M,K] @ W[N,K]^T + bias ----------------
// 128x64 tile, 8m x 4n per thread. f32x2 inner: a m-pairs natural LDS.64
// (As padded to 130 -> 8B aligned, conflict-free), w via ONE conflict-free
// LDS.128 (16B lane stride) + 4 register dup-packs. 16 FFMA2 : 5 LDS per kk.
__global__ void __launch_bounds__(256, 2) gemm_kernel(
    const float* __restrict__ A, const int* __restrict__ gather,
    const float* __restrict__ W, const float* __restrict__ bias,
    float* __restrict__ C, int M, int N, int K)
{
    __shared__ __align__(16) float As[32][130];   // [kk][m] pad->8B-aligned pairs
    __shared__ __align__(16) float Ws[32][68];    // [kk][n]

    const int tid = threadIdx.x;
    const int tx = tid & 15;          // n group: 4 cols
    const int ty = tid >> 4;          // m group: 8 rows
    const int m0 = blockIdx.y * 128;
    const int n0 = blockIdx.x * 64;

    const int sq = tid & 7;           // k-quad 0..7 (32 k = 8 quads)
    const int sr = tid >> 3;          // 0..31

    // row bases (gather resolved once)
    const float* arow[4];
    #pragma unroll
    for (int r = 0; r < 4; ++r) {
        int am = m0 + sr + 32 * r;
        if (gather) am = gather[am];
        arow[r] = A + (size_t)am * K;
    }
    const float* wrow[2];
    #pragma unroll
    for (int r = 0; r < 2; ++r)
        wrow[r] = W + (size_t)(n0 + sr + 32 * r) * K;

    ull acc[4][4];                    // [m-pair][n]
    #pragma unroll
    for (int mp = 0; mp < 4; ++mp)
        #pragma unroll
        for (int n = 0; n < 4; ++n) acc[mp][n] = 0ull;

    const int Kiter = (K + 31) >> 5;

    float4 pa[4], pw[2];
    {   // prefetch first tile
        int k = sq * 4;
        #pragma unroll
        for (int r = 0; r < 4; ++r) {
            if (k + 3 < K) pa[r] = *(const float4*)(arow[r] + k);
            else {
                float4 z = {0.f,0.f,0.f,0.f};
                #pragma unroll
                for (int j = 0; j < 4; ++j) if (k + j < K) ((float*)&z)[j] = arow[r][k + j];
                pa[r] = z;
            }
        }
        #pragma unroll
        for (int r = 0; r < 2; ++r) {
            if (k + 3 < K) pw[r] = *(const float4*)(wrow[r] + k);
            else {
                float4 z = {0.f,0.f,0.f,0.f};
                #pragma unroll
                for (int j = 0; j < 4; ++j) if (k + j < K) ((float*)&z)[j] = wrow[r][k + j];
                pw[r] = z;
            }
        }
    }

    for (int ki = 0; ki < Kiter; ++ki) {
        // ---- store staged tile (transpose; consecutive-bank STS) ----
        #pragma unroll
        for (int r = 0; r < 4; ++r) {
            int mm = sr + 32 * r;
            As[sq * 4 + 0][mm] = pa[r].x;
            As[sq * 4 + 1][mm] = pa[r].y;
            As[sq * 4 + 2][mm] = pa[r].z;
            As[sq * 4 + 3][mm] = pa[r].w;
        }
        #pragma unroll
        for (int r = 0; r < 2; ++r) {
            int nn = sr + 32 * r;
            Ws[sq * 4 + 0][nn] = pw[r].x;
            Ws[sq * 4 + 1][nn] = pw[r].y;
            Ws[sq * 4 + 2][nn] = pw[r].z;
            Ws[sq * 4 + 3][nn] = pw[r].w;
        }
        __syncthreads();

        // ---- prefetch next tile ----
        if (ki + 1 < Kiter) {
            int k = (ki + 1) * 32 + sq * 4;
            #pragma unroll
            for (int r = 0; r < 4; ++r) {
                if (k + 3 < K) pa[r] = *(const float4*)(arow[r] + k);
                else {
                    float4 z = {0.f,0.f,0.f,0.f};
                    #pragma unroll
                    for (int j = 0; j < 4; ++j) if (k + j < K) ((float*)&z)[j] = arow[r][k + j];
                    pa[r] = z;
                }
            }
            #pragma unroll
            for (int r = 0; r < 2; ++r) {
                if (k + 3 < K) pw[r] = *(const float4*)(wrow[r] + k);
                else {
                    float4 z = {0.f,0.f,0.f,0.f};
                    #pragma unroll
                    for (int j = 0; j < 4; ++j) if (k + j < K) ((float*)&z)[j] = wrow[r][k + j];
                    pw[r] = z;
                }
            }
        }

        // ---- compute: 16 FFMA2 + 4 LDS.64 + 1 LDS.128 + 4 packs per kk ----
        #pragma unroll
        for (int kk = 0; kk < 32; ++kk) {
            ull a[4];
            a[0] = *(const ull*)&As[kk][ty * 8 + 0];
            a[1] = *(const ull*)&As[kk][ty * 8 + 2];
            a[2] = *(const ull*)&As[kk][ty * 8 + 4];
            a[3] = *(const ull*)&As[kk][ty * 8 + 6];
            float4 wv = *(const float4*)&Ws[kk][tx * 4];
            ull w[4];
            w[0] = pack2(wv.x, wv.x);
            w[1] = pack2(wv.y, wv.y);
            w[2] = pack2(wv.z, wv.z);
            w[3] = pack2(wv.w, wv.w);
            #pragma unroll
            for (int mp = 0; mp < 4; ++mp)
                #pragma unroll
                for (int n = 0; n < 4; ++n)
                    acc[mp][n] = ffma2(a[mp], w[n], acc[mp][n]);
        }
        __syncthreads();
    }

    // ---- epilogue ----
    float bs[4];
    #pragma unroll
    for (int n = 0; n < 4; ++n) bs[n] = bias[n0 + tx * 4 + n];

    #pragma unroll
    for (int mp = 0; mp < 4; ++mp) {
        float2 v[4];
        #pragma unroll
        for (int n = 0; n < 4; ++n) v[n] = unpack2(acc[mp][n]);
        size_t r0 = (size_t)(m0 + ty * 8 + mp * 2 + 0) * N + n0 + tx * 4;
        size_t r1 = (size_t)(m0 + ty * 8 + mp * 2 + 1) * N + n0 + tx * 4;
        float4 o;
        o.x = v[0].x + bs[0]; o.y = v[1].x + bs[1]; o.z = v[2].x + bs[2]; o.w = v[3].x + bs[3];
        *(float4*)&C[r0] = o;
        o.x = v[0].y + bs[0]; o.y = v[1].y + bs[1]; o.z = v[2].y + bs[2]; o.w = v[3].y + bs[3];
        *(float4*)&C[r1] = o;
    }
}

// ---------------- persistent GRU recurrence (R3 version: f32x2, cp.async, 4x128k) ----------------
#define RS_WT    0
#define RS_HT    (512 * 20 * 4)                    // 40960
#define RS_RED   (RS_HT + 2 * 128 * 64 * 4)        // 40960 + 65536 = 106496
#define RS_XPS   (RS_RED + 32 * 8 * 12 * 8)        // + 24576 = 131072
#define RS_POOL  (RS_XPS + 192 * 16)               // + 3072 = 134144
#define RS_TOTAL (RS_POOL + 1024)                  // 135168

__global__ void __launch_bounds__(256) recur_kernel(
    const float* __restrict__ xp, const float* __restrict__ Whh,
    const float* __restrict__ bhh, float* __restrict__ hT,
    float* __restrict__ hist, float* __restrict__ pooled)
{
    extern __shared__ char smem_raw[];
    float* wt   = (float*)(smem_raw + RS_WT);      // [k][20]
    float* h_ts = (float*)(smem_raw + RS_HT);      // [2][128][64]
    ull*   red  = (ull*)  (smem_raw + RS_RED);     // [pos32][ks8][12]
    float* xps  = (float*)(smem_raw + RS_XPS);     // [3][64] float4
    float* pool = (float*)(smem_raw + RS_POOL);    // [4][64]

    const int tid = threadIdx.x;
    const int u0  = blockIdx.x * 4;

    for (int n = 0; n < 12; ++n) {
        int g = n >> 2, jj = n & 3;
        int posn = n + ((n >= 6) ? 2 : 0);
        const float* row = Whh + (size_t)(g * 512 + u0 + jj) * 512;
        for (int k = tid; k < 512; k += 256) wt[k * 20 + posn] = row[k];
    }

    const int b  = tid & 63;
    const int jj = tid >> 6;
    const float bh0 = bhh[u0 + jj];
    const float bh1 = bhh[512 + u0 + jj];
    const float bh2 = bhh[1024 + u0 + jj];

    const int lane = tid & 31;
    const int warp = tid >> 5;
    const int mg   = lane & 15;
    const int ng   = lane >> 4;

    const uint32_t hts_base = smem_u32(h_ts);
    __syncthreads();

    unsigned int epoch = 0;

    for (int t = 0; t < T_; ++t) {
        if (tid < 192) {
            int bb = tid & 63, g = tid >> 6;
            *(float4*)&xps[(g * 64 + bb) * 4] =
                *(const float4*)(xp + ((size_t)t * 64 + bb) * G3H_ + g * 512 + u0);
        }

        ull acc[4][3];
        #pragma unroll
        for (int m = 0; m < 4; ++m)
            #pragma unroll
            for (int np = 0; np < 3; ++np) acc[m][np] = 0ull;

        const float* hp = hT + (size_t)((t - 1) & 1) * 512 * 64;

        if (t > 0) {
            {   // stage chunk 0
                uint32_t dst = hts_base;
                #pragma unroll
                for (int q = 0; q < 8; ++q) {
                    int idx = tid + q * 256;
                    cp_async16(dst + idx * 16, hp + idx * 4);
                }
                asm volatile("cp.async.commit_group;" ::: "memory");
            }
            #pragma unroll 1
            for (int c = 0; c < 4; ++c) {
                __syncthreads();
                if (c < 3) {
                    uint32_t dst = hts_base + ((c + 1) & 1) * 32768;
                    const float* src = hp + (c + 1) * 8192;
                    #pragma unroll
                    for (int q = 0; q < 8; ++q) {
                        int idx = tid + q * 256;
                        cp_async16(dst + idx * 16, src + idx * 4);
                    }
                    asm volatile("cp.async.commit_group;" ::: "memory");
                    asm volatile("cp.async.wait_group 1;" ::: "memory");
                } else {
                    asm volatile("cp.async.wait_group 0;" ::: "memory");
                }
                __syncthreads();

                const float* hb = h_ts + (c & 1) * 8192;
                #pragma unroll
                for (int i = 0; i < 16; ++i) {
                    int kk = warp * 16 + i;
                    int k  = c * 128 + kk;
                    float4 h4 = *(const float4*)&hb[kk * 64 + mg * 4];
                    const float* wr = &wt[k * 20 + ng * 8];
                    ull wp0 = *(const ull*)(wr + 0);
                    ull wp1 = *(const ull*)(wr + 2);
                    ull wp2 = *(const ull*)(wr + 4);
                    ull hd;
                    hd = pack2(h4.x, h4.x);
                    acc[0][0] = ffma2(hd, wp0, acc[0][0]);
                    acc[0][1] = ffma2(hd, wp1, acc[0][1]);
                    acc[0][2] = ffma2(hd, wp2, acc[0][2]);
                    hd = pack2(h4.y, h4.y);
                    acc[1][0] = ffma2(hd, wp0, acc[1][0]);
                    acc[1][1] = ffma2(hd, wp1, acc[1][1]);
                    acc[1][2] = ffma2(hd, wp2, acc[1][2]);
                    hd = pack2(h4.z, h4.z);
                    acc[2][0] = ffma2(hd, wp0, acc[2][0]);
                    acc[2][1] = ffma2(hd, wp1, acc[2][1]);
                    acc[2][2] = ffma2(hd, wp2, acc[2][2]);
                    hd = pack2(h4.w, h4.w);
                    acc[3][0] = ffma2(hd, wp0, acc[3][0]);
                    acc[3][1] = ffma2(hd, wp1, acc[3][1]);
                    acc[3][2] = ffma2(hd, wp2, acc[3][2]);
                }
            }
        }

        __syncthreads();
        {
            int pos = mg * 2 + ng;
            ull* rp = &red[(pos * 8 + warp) * 12];
            #pragma unroll
            for (int m = 0; m < 4; ++m)
                #pragma unroll
                for (int np = 0; np < 3; ++np) rp[m * 3 + np] = acc[m][np];
        }
        __syncthreads();

        const float* redf = (const float*)red;
        float gh[3];
        #pragma unroll
        for (int g = 0; g < 3; ++g) {
            int n   = g * 4 + jj;
            int ngE = (n >= 6);
            int idx = n - ngE * 6;
            int npE = idx >> 1, half = idx & 1;
            int posE = (b >> 2) * 2 + ngE;
            int mE   = b & 3;
            int base = ((posE * 8) * 12 + mE * 3 + npE) * 2 + half;
            float s = 0.f;
            #pragma unroll
            for (int ks = 0; ks < 8; ++ks) s += redf[base + ks * 24];
            gh[g] = s;
        }

        float xr = xps[(0 * 64 + b) * 4 + jj];
        float xz = xps[(1 * 64 + b) * 4 + jj];
        float xn = xps[(2 * 64 + b) * 4 + jj];
        float hprev = (t > 0) ? __ldcg(&hp[(u0 + jj) * 64 + b]) : 0.f;

        float r = 1.f / (1.f + __expf(-(xr + gh[0] + bh0)));
        float z = 1.f / (1.f + __expf(-(xz + gh[1] + bh1)));
        float nn = tanhf(xn + r * (gh[2] + bh2));
        float hnew = (1.f - z) * nn + z * hprev;

        hT[(size_t)(t & 1) * 512 * 64 + (u0 + jj) * 64 + b] = hnew;
        if (hist) hist[((size_t)t * 64 + b) * 512 + u0 + jj] = hnew;

        if (pooled) {
            pool[jj * 64 + b] = hnew;
            __syncthreads();
            if (tid < 4) {
                float s = 0.f;
                #pragma unroll 8
                for (int q = 0; q < 64; ++q) s += pool[tid * 64 + q];
                pooled[t * 512 + u0 + tid] = s * (1.0f / 64.0f);
            }
        }

        if (t < T_ - 1) grid_barrier(&epoch);
    }
}

// ---------------- final FC ----------------
__global__ void fc_kernel(const float* __restrict__ pooled, const float* __restrict__ fcW,
                          const float* __restrict__ fcb, float* __restrict__ out)
{
    int t    = blockIdx.x;
    int lane = threadIdx.x;
    float acc[L_];
    #pragma unroll
    for (int l = 0; l < L_; ++l) acc[l] = 0.f;
    for (int k = lane; k < 512; k += 32) {
        float p = pooled[t * 512 + k];
        #pragma unroll
        for (int l = 0; l < L_; ++l) acc[l] = fmaf(p, fcW[l * 512 + k], acc[l]);
    }
    #pragma unroll
    for (int l = 0; l < L_; ++l) {
        #pragma unroll
        for (int off = 16; off > 0; off >>= 1)
            acc[l] += __shfl_down_sync(0xffffffffu, acc[l], off);
    }
    if (lane == 0) {
        #pragma unroll
        for (int l = 0; l < L_; ++l) out[t * L_ + l] = acc[l] + fcb[l];
    }
}

// ---------------- launch ----------------
extern "C" void kernel_launch(void* const* d_in, const int* in_sizes, int n_in,
                              void* d_out, int out_size)
{
    const int*   texts = (const int*)  d_in[0];
    const float* emb   = (const float*)d_in[1];
    const float* Wih0  = (const float*)d_in[2];
    const float* Whh0  = (const float*)d_in[3];
    const float* bih0  = (const float*)d_in[4];
    const float* bhh0  = (const float*)d_in[5];
    const float* Wih1  = (const float*)d_in[6];
    const float* Whh1  = (const float*)d_in[7];
    const float* bih1  = (const float*)d_in[8];
    const float* bhh1  = (const float*)d_in[9];
    const float* fcW   = (const float*)d_in[10];
    const float* fcb   = (const float*)d_in[11];
    float* out = (float*)d_out;

    float *xp0, *xp1, *h1, *hT, *pooled;
    cudaGetSymbolAddress((void**)&xp0,    g_xp0);
    cudaGetSymbolAddress((void**)&xp1,    g_xp1);
    cudaGetSymbolAddress((void**)&h1,     g_h1);
    cudaGetSymbolAddress((void**)&hT,     g_hT);
    cudaGetSymbolAddress((void**)&pooled, g_pooled);

    static bool attr_set = false;
    if (!attr_set) {
        cudaFuncSetAttribute(recur_kernel,
                             cudaFuncAttributeMaxDynamicSharedMemorySize, RS_TOTAL);
        attr_set = true;
    }

    const int M = T_ * B_;                  // 32768
    dim3 ggrid(G3H_ / 64, M / 128);         // (24, 256)

    // layer 0 input projection (embedding gather fused)
    gemm_kernel<<<ggrid, 256>>>(emb, texts, Wih0, bih0, xp0, M, G3H_, E_);

    // layer 0 recurrence -> h1 history ([t*B+b][H] for the next GEMM)
    init_kernel<<<1, 1>>>();
    recur_kernel<<<NBLK, NTHR, RS_TOTAL>>>(xp0, Whh0, bhh0, hT, h1, nullptr);

    // layer 1 input projection
    gemm_kernel<<<ggrid, 256>>>(h1, nullptr, Wih1, bih1, xp1, M, G3H_, H_);

    // layer 1 recurrence + batch-mean pooling
    init_kernel<<<1, 1>>>();
    recur_kernel<<<NBLK, NTHR, RS_TOTAL>>>(xp1, Whh1, bhh1, hT, nullptr, pooled);

    // final projection
    fc_kernel<<<T_, 32>>>(pooled, fcW, fcb, out);
}

// round 8
// speedup vs baseline: 1.7680x; 1.2660x over previous
#include <cuda_runtime.h>
#include <cstddef>
#include <cstdint>

#define T_   512
#define B_   64
#define E_   300
#define H_   512
#define L_   5
#define G3H_ 1536
#define NBLK 128
#define NTHR 256

typedef unsigned long long ull;

// ---------------- scratch (no allocations allowed) ----------------
__device__ float g_xp0[(size_t)T_ * B_ * G3H_];   // 201 MB
__device__ float g_xp1[(size_t)T_ * B_ * G3H_];   // 201 MB
__device__ float g_h1 [(size_t)T_ * B_ * H_];     // 67 MB  (layer0 history, [t*B+b][H])
__device__ float g_hT [2 * H_ * B_];              // h double buffer, [buf][bg][k512][b16]
__device__ float g_pooledp[4 * T_ * H_];          // per-bg partial sums
__device__ unsigned int g_arrive;

__global__ void init_kernel() { g_arrive = 0u; }

// ---------------- f32x2 helpers (FFMA2 only reachable via PTX) ----------------
__device__ __forceinline__ ull ffma2(ull a, ull b, ull c) {
    ull d;
    asm("fma.rn.f32x2 %0, %1, %2, %3;" : "=l"(d) : "l"(a), "l"(b), "l"(c));
    return d;
}
__device__ __forceinline__ ull pack2(float lo, float hi) {
    ull d;
    asm("mov.b64 %0, {%1, %2};" : "=l"(d) : "f"(lo), "f"(hi));
    return d;
}
__device__ __forceinline__ float2 unpack2(ull v) {
    float2 r;
    asm("mov.b64 {%0, %1}, %2;" : "=f"(r.x), "=f"(r.y) : "l"(v));
    return r;
}
__device__ __forceinline__ uint32_t smem_u32(const void* p) {
    uint32_t a;
    asm("{ .reg .u64 t; cvta.to.shared.u64 t, %1; cvt.u32.u64 %0, t; }" : "=r"(a) : "l"(p));
    return a;
}
__device__ __forceinline__ void cp_async16(uint32_t dst, const void* src) {
    asm volatile("cp.async.cg.shared.global [%0], [%1], 16;" :: "r"(dst), "l"(src));
}

// ---------------- grid-wide barrier (all 128 CTAs co-resident, 1 CTA/SM) ----------------
__device__ __forceinline__ void grid_barrier(unsigned int* epoch) {
    __syncthreads();
    if (threadIdx.x == 0) {
        __threadfence();
        unsigned int target = (*epoch + 1u) * NBLK;
        atomicAdd(&g_arrive, 1u);
        while (*((volatile unsigned int*)&g_arrive) < target) { }
        __threadfence();
    }
    __syncthreads();
    ++(*epoch);
}

// ---------------- fp32 GEMM: C[M,N] = A[M,K] @ W[N,K]^T + bias (R7, unchanged) ----------------
__global__ void __launch_bounds__(256, 2) gemm_kernel(
    const float* __restrict__ A, const int* __restrict__ gather,
    const float* __restrict__ W, const float* __restrict__ bias,
    float* __restrict__ C, int M, int N, int K)
{
    __shared__ __align__(16) float As[32][130];
    __shared__ __align__(16) float Ws[32][68];

    const int tid = threadIdx.x;
    const int tx = tid & 15;
    const int ty = tid >> 4;
    const int m0 = blockIdx.y * 128;
    const int n0 = blockIdx.x * 64;

    const int sq = tid & 7;
    const int sr = tid >> 3;

    const float* arow[4];
    #pragma unroll
    for (int r = 0; r < 4; ++r) {
        int am = m0 + sr + 32 * r;
        if (gather) am = gather[am];
        arow[r] = A + (size_t)am * K;
    }
    const float* wrow[2];
    #pragma unroll
    for (int r = 0; r < 2; ++r)
        wrow[r] = W + (size_t)(n0 + sr + 32 * r) * K;

    ull acc[4][4];
    #pragma unroll
    for (int mp = 0; mp < 4; ++mp)
        #pragma unroll
        for (int n = 0; n < 4; ++n) acc[mp][n] = 0ull;

    const int Kiter = (K + 31) >> 5;

    float4 pa[4], pw[2];
    {
        int k = sq * 4;
        #pragma unroll
        for (int r = 0; r < 4; ++r) {
            if (k + 3 < K) pa[r] = *(const float4*)(arow[r] + k);
            else {
                float4 z = {0.f,0.f,0.f,0.f};
                #pragma unroll
                for (int j = 0; j < 4; ++j) if (k + j < K) ((float*)&z)[j] = arow[r][k + j];
                pa[r] = z;
            }
        }
        #pragma unroll
        for (int r = 0; r < 2; ++r) {
            if (k + 3 < K) pw[r] = *(const float4*)(wrow[r] + k);
            else {
                float4 z = {0.f,0.f,0.f,0.f};
                #pragma unroll
                for (int j = 0; j < 4; ++j) if (k + j < K) ((float*)&z)[j] = wrow[r][k + j];
                pw[r] = z;
            }
        }
    }

    for (int ki = 0; ki < Kiter; ++ki) {
        #pragma unroll
        for (int r = 0; r < 4; ++r) {
            int mm = sr + 32 * r;
            As[sq * 4 + 0][mm] = pa[r].x;
            As[sq * 4 + 1][mm] = pa[r].y;
            As[sq * 4 + 2][mm] = pa[r].z;
            As[sq * 4 + 3][mm] = pa[r].w;
        }
        #pragma unroll
        for (int r = 0; r < 2; ++r) {
            int nn = sr + 32 * r;
            Ws[sq * 4 + 0][nn] = pw[r].x;
            Ws[sq * 4 + 1][nn] = pw[r].y;
            Ws[sq * 4 + 2][nn] = pw[r].z;
            Ws[sq * 4 + 3][nn] = pw[r].w;
        }
        __syncthreads();

        if (ki + 1 < Kiter) {
            int k = (ki + 1) * 32 + sq * 4;
            #pragma unroll
            for (int r = 0; r < 4; ++r) {
                if (k + 3 < K) pa[r] = *(const float4*)(arow[r] + k);
                else {
                    float4 z = {0.f,0.f,0.f,0.f};
                    #pragma unroll
                    for (int j = 0; j < 4; ++j) if (k + j < K) ((float*)&z)[j] = arow[r][k + j];
                    pa[r] = z;
                }
            }
            #pragma unroll
            for (int r = 0; r < 2; ++r) {
                if (k + 3 < K) pw[r] = *(const float4*)(wrow[r] + k);
                else {
                    float4 z = {0.f,0.f,0.f,0.f};
                    #pragma unroll
                    for (int j = 0; j < 4; ++j) if (k + j < K) ((float*)&z)[j] = wrow[r][k + j];
                    pw[r] = z;
                }
            }
        }

        #pragma unroll
        for (int kk = 0; kk < 32; ++kk) {
            ull a[4];
            a[0] = *(const ull*)&As[kk][ty * 8 + 0];
            a[1] = *(const ull*)&As[kk][ty * 8 + 2];
            a[2] = *(const ull*)&As[kk][ty * 8 + 4];
            a[3] = *(const ull*)&As[kk][ty * 8 + 6];
            float4 wv = *(const float4*)&Ws[kk][tx * 4];
            ull w[4];
            w[0] = pack2(wv.x, wv.x);
            w[1] = pack2(wv.y, wv.y);
            w[2] = pack2(wv.z, wv.z);
            w[3] = pack2(wv.w, wv.w);
            #pragma unroll
            for (int mp = 0; mp < 4; ++mp)
                #pragma unroll
                for (int n = 0; n < 4; ++n)
                    acc[mp][n] = ffma2(a[mp], w[n], acc[mp][n]);
        }
        __syncthreads();
    }

    float bs[4];
    #pragma unroll
    for (int n = 0; n < 4; ++n) bs[n] = bias[n0 + tx * 4 + n];

    #pragma unroll
    for (int mp = 0; mp < 4; ++mp) {
        float2 v[4];
        #pragma unroll
        for (int n = 0; n < 4; ++n) v[n] = unpack2(acc[mp][n]);
        size_t r0 = (size_t)(m0 + ty * 8 + mp * 2 + 0) * N + n0 + tx * 4;
        size_t r1 = (size_t)(m0 + ty * 8 + mp * 2 + 1) * N + n0 + tx * 4;
        float4 o;
        o.x = v[0].x + bs[0]; o.y = v[1].x + bs[1]; o.z = v[2].x + bs[2]; o.w = v[3].x + bs[3];
        *(float4*)&C[r0] = o;
        o.x = v[0].y + bs[0]; o.y = v[1].y + bs[1]; o.z = v[2].y + bs[2]; o.w = v[3].y + bs[3];
        *(float4*)&C[r1] = o;
    }
}

// ---------------- persistent GRU recurrence: 2-D decomposition ----------------
// 128 CTAs = 32 unit-groups x 4 batch-groups. CTA owns 16 units (48 gate rows)
// x 16 batches. h global layout [buf][bg][k512][b16]; per-CTA h read 32KB/step
// (4x less L2 broadcast). h_prev register-carried. Compute thread: warp=ks
// (k-split 8, 32k per chunk), lane = bq(4 batch-quads) x rg(8 row-triples).
// Per k: 1 LDS.128 h + 3 LDS.64 w-pairs + 12 FFMA2 (same profile as R7).

#define RS_WT    0                                  // [k512][48] = 98304 B
#define RS_HT    98304                              // [2 chunks][256k][16b] = 32768 B
#define RS_RED   131072                             // [ks8][bq4][rg8][13 ull] = 26624 B
#define RS_XPS   157696                             // [3g][16b][16u] = 3072 B
#define RS_POOL  160768                             // [16u][16b] = 1024 B
#define RS_TOTAL 161792

__global__ void __launch_bounds__(256) recur_kernel(
    const float* __restrict__ xp, const float* __restrict__ Whh,
    const float* __restrict__ bhh, float* __restrict__ hg,
    float* __restrict__ hist, float* __restrict__ pooledp)
{
    extern __shared__ char smem_raw[];
    float* wt   = (float*)(smem_raw + RS_WT);
    float* h_ts = (float*)(smem_raw + RS_HT);
    ull*   red  = (ull*)  (smem_raw + RS_RED);
    float* xps  = (float*)(smem_raw + RS_XPS);
    float* pool = (float*)(smem_raw + RS_POOL);

    const int tid = threadIdx.x;
    const int ug  = blockIdx.x >> 2;
    const int bg  = blockIdx.x & 3;
    const int u0  = ug * 16;
    const int b0  = bg * 16;

    // stage W slice: wt[k*48 + p*2 + h], p = g*8 + j/2, h = j&1, row (g, u0+j)
    for (int r = 0; r < 48; ++r) {
        int g = r >> 4, j = r & 15;
        int p = g * 8 + (j >> 1), hh = j & 1;
        const float* row = Whh + (size_t)(g * 512 + u0 + j) * 512;
        for (int k = tid; k < 512; k += 256) wt[k * 48 + p * 2 + hh] = row[k];
    }

    // epilogue ids: one output (b, uu) per thread
    const int b  = tid & 15;
    const int uu = tid >> 4;
    const float bh0 = bhh[u0 + uu];
    const float bh1 = bhh[512 + u0 + uu];
    const float bh2 = bhh[1024 + u0 + uu];

    // compute ids
    const int lane = tid & 31;
    const int ks   = tid >> 5;       // k-split warp
    const int bq   = lane & 3;       // batch quad
    const int rg   = lane >> 2;      // row triple (3 pairs)

    const uint32_t hts_base = smem_u32(h_ts);
    __syncthreads();

    unsigned int epoch = 0;
    float hprev = 0.f;

    for (int t = 0; t < T_; ++t) {
        // stage xp[t] slice: [g][b][16u]
        if (tid < 192) {
            int g = tid >> 6, rem = tid & 63;
            int bb = rem >> 2, q = rem & 3;
            *(float4*)&xps[g * 256 + bb * 16 + q * 4] =
                *(const float4*)(xp + ((size_t)t * 64 + b0 + bb) * G3H_ + g * 512 + u0 + q * 4);
        }

        ull acc[4][3];
        #pragma unroll
        for (int m = 0; m < 4; ++m)
            #pragma unroll
            for (int pp = 0; pp < 3; ++pp) acc[m][pp] = 0ull;

        if (t > 0) {
            const float* hp = hg + ((size_t)((t - 1) & 1) * 4 + bg) * 8192;
            // issue both 16KB chunks
            #pragma unroll
            for (int c = 0; c < 2; ++c) {
                uint32_t dst = hts_base + c * 16384;
                const float* src = hp + c * 4096;
                #pragma unroll
                for (int q = 0; q < 4; ++q) {
                    int idx = tid + q * 256;
                    cp_async16(dst + idx * 16, src + idx * 4);
                }
                asm volatile("cp.async.commit_group;" ::: "memory");
            }
            #pragma unroll 1
            for (int c = 0; c < 2; ++c) {
                if (c == 0) asm volatile("cp.async.wait_group 1;" ::: "memory");
                else        asm volatile("cp.async.wait_group 0;" ::: "memory");
                __syncthreads();

                const float* hb = h_ts + c * 4096;
                #pragma unroll
                for (int i = 0; i < 32; ++i) {
                    int kk = ks * 32 + i;           // 0..255 within chunk
                    int k  = c * 256 + kk;
                    float4 h4 = *(const float4*)&hb[kk * 16 + bq * 4];
                    const float* wr = &wt[k * 48 + rg * 6];
                    ull wp0 = *(const ull*)(wr + 0);
                    ull wp1 = *(const ull*)(wr + 2);
                    ull wp2 = *(const ull*)(wr + 4);
                    ull hd;
                    hd = pack2(h4.x, h4.x);
                    acc[0][0] = ffma2(hd, wp0, acc[0][0]);
                    acc[0][1] = ffma2(hd, wp1, acc[0][1]);
                    acc[0][2] = ffma2(hd, wp2, acc[0][2]);
                    hd = pack2(h4.y, h4.y);
                    acc[1][0] = ffma2(hd, wp0, acc[1][0]);
                    acc[1][1] = ffma2(hd, wp1, acc[1][1]);
                    acc[1][2] = ffma2(hd, wp2, acc[1][2]);
                    hd = pack2(h4.z, h4.z);
                    acc[2][0] = ffma2(hd, wp0, acc[2][0]);
                    acc[2][1] = ffma2(hd, wp1, acc[2][1]);
                    acc[2][2] = ffma2(hd, wp2, acc[2][2]);
                    hd = pack2(h4.w, h4.w);
                    acc[3][0] = ffma2(hd, wp0, acc[3][0]);
                    acc[3][1] = ffma2(hd, wp1, acc[3][1]);
                    acc[3][2] = ffma2(hd, wp2, acc[3][2]);
                }
            }
        }

        // ---- cross-ks reduction ----
        __syncthreads();   // also covers xps staging when t==0
        {
            ull* rp = &red[(ks * 32 + bq * 8 + rg) * 13];
            #pragma unroll
            for (int m = 0; m < 4; ++m)
                #pragma unroll
                for (int pp = 0; pp < 3; ++pp) rp[m * 3 + pp] = acc[m][pp];
        }
        __syncthreads();

        // ---- epilogue: thread (b, uu) ----
        const float* redf = (const float*)red;
        float gh[3];
        #pragma unroll
        for (int g = 0; g < 3; ++g) {
            int p = g * 8 + (uu >> 1), half = uu & 1;
            int rgE = p / 3, ppE = p % 3;
            int base = ((b >> 2) * 8 + rgE) * 26 + (b & 3) * 6 + ppE * 2 + half;
            float s = 0.f;
            #pragma unroll
            for (int kw = 0; kw < 8; ++kw) s += redf[base + kw * 832];
            gh[g] = s;
        }

        float xr = xps[0 * 256 + b * 16 + uu];
        float xz = xps[1 * 256 + b * 16 + uu];
        float xn = xps[2 * 256 + b * 16 + uu];

        float r = 1.f / (1.f + __expf(-(xr + gh[0] + bh0)));
        float z = 1.f / (1.f + __expf(-(xz + gh[1] + bh1)));
        float nn = tanhf(xn + r * (gh[2] + bh2));
        float hnew = (1.f - z) * nn + z * hprev;
        hprev = hnew;

        hg[((size_t)(t & 1) * 4 + bg) * 8192 + (u0 + uu) * 16 + b] = hnew;
        if (hist) hist[((size_t)t * 64 + b0 + b) * 512 + u0 + uu] = hnew;

        if (pooledp) {
            pool[uu * 16 + b] = hnew;
            __syncthreads();
            if (tid < 16) {
                float s = 0.f;
                #pragma unroll
                for (int q = 0; q < 16; ++q) s += pool[tid * 16 + q];
                pooledp[(size_t)bg * T_ * 512 + t * 512 + u0 + tid] = s;
            }
        }

        if (t < T_ - 1) grid_barrier(&epoch);
    }
}

// ---------------- final FC: combine 4 pooled partials + project ----------------
__global__ void fc_kernel(const float* __restrict__ pooledp, const float* __restrict__ fcW,
                          const float* __restrict__ fcb, float* __restrict__ out)
{
    int t    = blockIdx.x;
    int lane = threadIdx.x;
    float acc[L_];
    #pragma unroll
    for (int l = 0; l < L_; ++l) acc[l] = 0.f;
    for (int k = lane; k < 512; k += 32) {
        float p = pooledp[0 * T_ * 512 + t * 512 + k]
                + pooledp[1 * T_ * 512 + t * 512 + k]
                + pooledp[2 * T_ * 512 + t * 512 + k]
                + pooledp[3 * T_ * 512 + t * 512 + k];
        p *= (1.0f / 64.0f);
        #pragma unroll
        for (int l = 0; l < L_; ++l) acc[l] = fmaf(p, fcW[l * 512 + k], acc[l]);
    }
    #pragma unroll
    for (int l = 0; l < L_; ++l) {
        #pragma unroll
        for (int off = 16; off > 0; off >>= 1)
            acc[l] += __shfl_down_sync(0xffffffffu, acc[l], off);
    }
    if (lane == 0) {
        #pragma unroll
        for (int l = 0; l < L_; ++l) out[t * L_ + l] = acc[l] + fcb[l];
    }
}

// ---------------- launch ----------------
extern "C" void kernel_launch(void* const* d_in, const int* in_sizes, int n_in,
                              void* d_out, int out_size)
{
    const int*   texts = (const int*)  d_in[0];
    const float* emb   = (const float*)d_in[1];
    const float* Wih0  = (const float*)d_in[2];
    const float* Whh0  = (const float*)d_in[3];
    const float* bih0  = (const float*)d_in[4];
    const float* bhh0  = (const float*)d_in[5];
    const float* Wih1  = (const float*)d_in[6];
    const float* Whh1  = (const float*)d_in[7];
    const float* bih1  = (const float*)d_in[8];
    const float* bhh1  = (const float*)d_in[9];
    const float* fcW   = (const float*)d_in[10];
    const float* fcb   = (const float*)d_in[11];
    float* out = (float*)d_out;

    float *xp0, *xp1, *h1, *hT, *pooledp;
    cudaGetSymbolAddress((void**)&xp0,     g_xp0);
    cudaGetSymbolAddress((void**)&xp1,     g_xp1);
    cudaGetSymbolAddress((void**)&h1,      g_h1);
    cudaGetSymbolAddress((void**)&hT,      g_hT);
    cudaGetSymbolAddress((void**)&pooledp, g_pooledp);

    static bool attr_set = false;
    if (!attr_set) {
        cudaFuncSetAttribute(recur_kernel,
                             cudaFuncAttributeMaxDynamicSharedMemorySize, RS_TOTAL);
        attr_set = true;
    }

    const int M = T_ * B_;                  // 32768
    dim3 ggrid(G3H_ / 64, M / 128);         // (24, 256)

    // layer 0 input projection (embedding gather fused)
    gemm_kernel<<<ggrid, 256>>>(emb, texts, Wih0, bih0, xp0, M, G3H_, E_);

    // layer 0 recurrence -> h1 history ([t*B+b][H] for the next GEMM)
    init_kernel<<<1, 1>>>();
    recur_kernel<<<NBLK, NTHR, RS_TOTAL>>>(xp0, Whh0, bhh0, hT, h1, nullptr);

    // layer 1 input projection
    gemm_kernel<<<ggrid, 256>>>(h1, nullptr, Wih1, bih1, xp1, M, G3H_, H_);

    // layer 1 recurrence + partial batch-mean pooling
    init_kernel<<<1, 1>>>();
    recur_kernel<<<NBLK, NTHR, RS_TOTAL>>>(xp1, Whh1, bhh1, hT, nullptr, pooledp);

    // final projection
    fc_kernel<<<T_, 32>>>(pooledp, fcW, fcb, out);
}

// round 9
// speedup vs baseline: 1.7830x; 1.0084x over previous
#include <cuda_runtime.h>
#include <cstddef>
#include <cstdint>

#define T_   512
#define B_   64
#define E_   300
#define H_   512
#define L_   5
#define G3H_ 1536
#define NBLK 128
#define NTHR 256
#define GRPSZ 32      // CTAs per batch-group barrier

typedef unsigned long long ull;

// ---------------- scratch (no allocations allowed) ----------------
__device__ float g_xp0[(size_t)T_ * B_ * G3H_];   // 201 MB
__device__ float g_xp1[(size_t)T_ * B_ * G3H_];   // 201 MB
__device__ float g_h1 [(size_t)T_ * B_ * H_];     // 67 MB  (layer0 history, [t*B+b][H])
__device__ float g_hT [2 * H_ * B_];              // h double buffer, [buf][bg][k512][b16]
__device__ float g_pooledp[4 * T_ * H_];          // per-bg partial sums
__device__ unsigned int g_arrive4[4 * 32];        // one counter per bg, 128B apart

__global__ void init_kernel() {
    if (threadIdx.x < 4 * 32) g_arrive4[threadIdx.x] = 0u;
}

// ---------------- f32x2 helpers (FFMA2 only reachable via PTX) ----------------
__device__ __forceinline__ ull ffma2(ull a, ull b, ull c) {
    ull d;
    asm("fma.rn.f32x2 %0, %1, %2, %3;" : "=l"(d) : "l"(a), "l"(b), "l"(c));
    return d;
}
__device__ __forceinline__ ull pack2(float lo, float hi) {
    ull d;
    asm("mov.b64 %0, {%1, %2};" : "=l"(d) : "f"(lo), "f"(hi));
    return d;
}
__device__ __forceinline__ float2 unpack2(ull v) {
    float2 r;
    asm("mov.b64 {%0, %1}, %2;" : "=f"(r.x), "=f"(r.y) : "l"(v));
    return r;
}
__device__ __forceinline__ uint32_t smem_u32(const void* p) {
    uint32_t a;
    asm("{ .reg .u64 t; cvta.to.shared.u64 t, %1; cvt.u32.u64 %0, t; }" : "=r"(a) : "l"(p));
    return a;
}
__device__ __forceinline__ void cp_async16(uint32_t dst, const void* src) {
    asm volatile("cp.async.cg.shared.global [%0], [%1], 16;" :: "r"(dst), "l"(src));
}

// ---------------- per-group barrier (32 co-resident CTAs sharing one bg) ----------------
__device__ __forceinline__ void group_barrier(unsigned int* epoch, unsigned int* cnt) {
    __syncthreads();
    if (threadIdx.x == 0) {
        __threadfence();
        unsigned int target = (*epoch + 1u) * GRPSZ;
        atomicAdd(cnt, 1u);
        while (*((volatile unsigned int*)cnt) < target) { }
        __threadfence();
    }
    __syncthreads();
    ++(*epoch);
}

// ---------------- fp32 GEMM: C[M,N] = A[M,K] @ W[N,K]^T + bias (R7, unchanged) ----------------
__global__ void __launch_bounds__(256, 2) gemm_kernel(
    const float* __restrict__ A, const int* __restrict__ gather,
    const float* __restrict__ W, const float* __restrict__ bias,
    float* __restrict__ C, int M, int N, int K)
{
    __shared__ __align__(16) float As[32][130];
    __shared__ __align__(16) float Ws[32][68];

    const int tid = threadIdx.x;
    const int tx = tid & 15;
    const int ty = tid >> 4;
    const int m0 = blockIdx.y * 128;
    const int n0 = blockIdx.x * 64;

    const int sq = tid & 7;
    const int sr = tid >> 3;

    const float* arow[4];
    #pragma unroll
    for (int r = 0; r < 4; ++r) {
        int am = m0 + sr + 32 * r;
        if (gather) am = gather[am];
        arow[r] = A + (size_t)am * K;
    }
    const float* wrow[2];
    #pragma unroll
    for (int r = 0; r < 2; ++r)
        wrow[r] = W + (size_t)(n0 + sr + 32 * r) * K;

    ull acc[4][4];
    #pragma unroll
    for (int mp = 0; mp < 4; ++mp)
        #pragma unroll
        for (int n = 0; n < 4; ++n) acc[mp][n] = 0ull;

    const int Kiter = (K + 31) >> 5;

    float4 pa[4], pw[2];
    {
        int k = sq * 4;
        #pragma unroll
        for (int r = 0; r < 4; ++r) {
            if (k + 3 < K) pa[r] = *(const float4*)(arow[r] + k);
            else {
                float4 z = {0.f,0.f,0.f,0.f};
                #pragma unroll
                for (int j = 0; j < 4; ++j) if (k + j < K) ((float*)&z)[j] = arow[r][k + j];
                pa[r] = z;
            }
        }
        #pragma unroll
        for (int r = 0; r < 2; ++r) {
            if (k + 3 < K) pw[r] = *(const float4*)(wrow[r] + k);
            else {
                float4 z = {0.f,0.f,0.f,0.f};
                #pragma unroll
                for (int j = 0; j < 4; ++j) if (k + j < K) ((float*)&z)[j] = wrow[r][k + j];
                pw[r] = z;
            }
        }
    }

    for (int ki = 0; ki < Kiter; ++ki) {
        #pragma unroll
        for (int r = 0; r < 4; ++r) {
            int mm = sr + 32 * r;
            As[sq * 4 + 0][mm] = pa[r].x;
            As[sq * 4 + 1][mm] = pa[r].y;
            As[sq * 4 + 2][mm] = pa[r].z;
            As[sq * 4 + 3][mm] = pa[r].w;
        }
        #pragma unroll
        for (int r = 0; r < 2; ++r) {
            int nn = sr + 32 * r;
            Ws[sq * 4 + 0][nn] = pw[r].x;
            Ws[sq * 4 + 1][nn] = pw[r].y;
            Ws[sq * 4 + 2][nn] = pw[r].z;
            Ws[sq * 4 + 3][nn] = pw[r].w;
        }
        __syncthreads();

        if (ki + 1 < Kiter) {
            int k = (ki + 1) * 32 + sq * 4;
            #pragma unroll
            for (int r = 0; r < 4; ++r) {
                if (k + 3 < K) pa[r] = *(const float4*)(arow[r] + k);
                else {
                    float4 z = {0.f,0.f,0.f,0.f};
                    #pragma unroll
                    for (int j = 0; j < 4; ++j) if (k + j < K) ((float*)&z)[j] = arow[r][k + j];
                    pa[r] = z;
                }
            }
            #pragma unroll
            for (int r = 0; r < 2; ++r) {
                if (k + 3 < K) pw[r] = *(const float4*)(wrow[r] + k);
                else {
                    float4 z = {0.f,0.f,0.f,0.f};
                    #pragma unroll
                    for (int j = 0; j < 4; ++j) if (k + j < K) ((float*)&z)[j] = wrow[r][k + j];
                    pw[r] = z;
                }
            }
        }

        #pragma unroll
        for (int kk = 0; kk < 32; ++kk) {
            ull a[4];
            a[0] = *(const ull*)&As[kk][ty * 8 + 0];
            a[1] = *(const ull*)&As[kk][ty * 8 + 2];
            a[2] = *(const ull*)&As[kk][ty * 8 + 4];
            a[3] = *(const ull*)&As[kk][ty * 8 + 6];
            float4 wv = *(const float4*)&Ws[kk][tx * 4];
            ull w[4];
            w[0] = pack2(wv.x, wv.x);
            w[1] = pack2(wv.y, wv.y);
            w[2] = pack2(wv.z, wv.z);
            w[3] = pack2(wv.w, wv.w);
            #pragma unroll
            for (int mp = 0; mp < 4; ++mp)
                #pragma unroll
                for (int n = 0; n < 4; ++n)
                    acc[mp][n] = ffma2(a[mp], w[n], acc[mp][n]);
        }
        __syncthreads();
    }

    float bs[4];
    #pragma unroll
    for (int n = 0; n < 4; ++n) bs[n] = bias[n0 + tx * 4 + n];

    #pragma unroll
    for (int mp = 0; mp < 4; ++mp) {
        float2 v[4];
        #pragma unroll
        for (int n = 0; n < 4; ++n) v[n] = unpack2(acc[mp][n]);
        size_t r0 = (size_t)(m0 + ty * 8 + mp * 2 + 0) * N + n0 + tx * 4;
        size_t r1 = (size_t)(m0 + ty * 8 + mp * 2 + 1) * N + n0 + tx * 4;
        float4 o;
        o.x = v[0].x + bs[0]; o.y = v[1].x + bs[1]; o.z = v[2].x + bs[2]; o.w = v[3].x + bs[3];
        *(float4*)&C[r0] = o;
        o.x = v[0].y + bs[0]; o.y = v[1].y + bs[1]; o.z = v[2].y + bs[2]; o.w = v[3].y + bs[3];
        *(float4*)&C[r1] = o;
    }
}

// ---------------- persistent GRU recurrence: 2-D decomposition, per-bg barrier ----------------
// 128 CTAs = 32 unit-groups x 4 batch-groups. The 4 bg chains are fully
// independent: barrier only spans the 32 CTAs of one bg (4x less atomic
// contention, no cross-group jitter coupling).

#define RS_WT    0                                  // [k512][48] = 98304 B
#define RS_HT    98304                              // [2 chunks][256k][16b] = 32768 B
#define RS_RED   131072                             // [ks8][bq4][rg8][13 ull] = 26624 B
#define RS_XPS   157696                             // [3g][16b][16u] = 3072 B
#define RS_TOTAL 160768

__global__ void __launch_bounds__(256) recur_kernel(
    const float* __restrict__ xp, const float* __restrict__ Whh,
    const float* __restrict__ bhh, float* __restrict__ hg,
    float* __restrict__ hist, float* __restrict__ pooledp)
{
    extern __shared__ char smem_raw[];
    float* wt   = (float*)(smem_raw + RS_WT);
    float* h_ts = (float*)(smem_raw + RS_HT);
    ull*   red  = (ull*)  (smem_raw + RS_RED);
    float* xps  = (float*)(smem_raw + RS_XPS);

    const int tid = threadIdx.x;
    const int ug  = blockIdx.x >> 2;
    const int bg  = blockIdx.x & 3;
    const int u0  = ug * 16;
    const int b0  = bg * 16;
    unsigned int* cnt = &g_arrive4[bg * 32];

    // stage W slice: wt[k*48 + p*2 + h], p = g*8 + j/2, h = j&1, row (g, u0+j)
    for (int r = 0; r < 48; ++r) {
        int g = r >> 4, j = r & 15;
        int p = g * 8 + (j >> 1), hh = j & 1;
        const float* row = Whh + (size_t)(g * 512 + u0 + j) * 512;
        for (int k = tid; k < 512; k += 256) wt[k * 48 + p * 2 + hh] = row[k];
    }

    // epilogue ids: one output (b, uu) per thread
    const int b  = tid & 15;
    const int uu = tid >> 4;
    const float bh0 = bhh[u0 + uu];
    const float bh1 = bhh[512 + u0 + uu];
    const float bh2 = bhh[1024 + u0 + uu];

    // compute ids
    const int lane = tid & 31;
    const int ks   = tid >> 5;       // k-split warp
    const int bq   = lane & 3;       // batch quad
    const int rg   = lane >> 2;      // row triple (3 pairs)

    const uint32_t hts_base = smem_u32(h_ts);
    __syncthreads();

    unsigned int epoch = 0;
    float hprev = 0.f;

    for (int t = 0; t < T_; ++t) {
        // stage xp[t] slice: [g][b][16u]
        if (tid < 192) {
            int g = tid >> 6, rem = tid & 63;
            int bb = rem >> 2, q = rem & 3;
            *(float4*)&xps[g * 256 + bb * 16 + q * 4] =
                *(const float4*)(xp + ((size_t)t * 64 + b0 + bb) * G3H_ + g * 512 + u0 + q * 4);
        }

        ull acc[4][3];
        #pragma unroll
        for (int m = 0; m < 4; ++m)
            #pragma unroll
            for (int pp = 0; pp < 3; ++pp) acc[m][pp] = 0ull;

        if (t > 0) {
            const float* hp = hg + ((size_t)((t - 1) & 1) * 4 + bg) * 8192;
            // issue both 16KB chunks
            #pragma unroll
            for (int c = 0; c < 2; ++c) {
                uint32_t dst = hts_base + c * 16384;
                const float* src = hp + c * 4096;
                #pragma unroll
                for (int q = 0; q < 4; ++q) {
                    int idx = tid + q * 256;
                    cp_async16(dst + idx * 16, src + idx * 4);
                }
                asm volatile("cp.async.commit_group;" ::: "memory");
            }
            #pragma unroll 1
            for (int c = 0; c < 2; ++c) {
                if (c == 0) asm volatile("cp.async.wait_group 1;" ::: "memory");
                else        asm volatile("cp.async.wait_group 0;" ::: "memory");
                __syncthreads();

                const float* hb = h_ts + c * 4096;
                #pragma unroll
                for (int i = 0; i < 32; ++i) {
                    int kk = ks * 32 + i;           // 0..255 within chunk
                    int k  = c * 256 + kk;
                    float4 h4 = *(const float4*)&hb[kk * 16 + bq * 4];
                    const float* wr = &wt[k * 48 + rg * 6];
                    ull wp0 = *(const ull*)(wr + 0);
                    ull wp1 = *(const ull*)(wr + 2);
                    ull wp2 = *(const ull*)(wr + 4);
                    ull hd;
                    hd = pack2(h4.x, h4.x);
                    acc[0][0] = ffma2(hd, wp0, acc[0][0]);
                    acc[0][1] = ffma2(hd, wp1, acc[0][1]);
                    acc[0][2] = ffma2(hd, wp2, acc[0][2]);
                    hd = pack2(h4.y, h4.y);
                    acc[1][0] = ffma2(hd, wp0, acc[1][0]);
                    acc[1][1] = ffma2(hd, wp1, acc[1][1]);
                    acc[1][2] = ffma2(hd, wp2, acc[1][2]);
                    hd = pack2(h4.z, h4.z);
                    acc[2][0] = ffma2(hd, wp0, acc[2][0]);
                    acc[2][1] = ffma2(hd, wp1, acc[2][1]);
                    acc[2][2] = ffma2(hd, wp2, acc[2][2]);
                    hd = pack2(h4.w, h4.w);
                    acc[3][0] = ffma2(hd, wp0, acc[3][0]);
                    acc[3][1] = ffma2(hd, wp1, acc[3][1]);
                    acc[3][2] = ffma2(hd, wp2, acc[3][2]);
                }
            }
        }

        // ---- cross-ks reduction ----
        __syncthreads();   // also covers xps staging when t==0
        {
            ull* rp = &red[(ks * 32 + bq * 8 + rg) * 13];
            #pragma unroll
            for (int m = 0; m < 4; ++m)
                #pragma unroll
                for (int pp = 0; pp < 3; ++pp) rp[m * 3 + pp] = acc[m][pp];
        }
        __syncthreads();

        // ---- epilogue: thread (b, uu) ----
        const float* redf = (const float*)red;
        float gh[3];
        #pragma unroll
        for (int g = 0; g < 3; ++g) {
            int p = g * 8 + (uu >> 1), half = uu & 1;
            int rgE = p / 3, ppE = p % 3;
            int base = ((b >> 2) * 8 + rgE) * 26 + (b & 3) * 6 + ppE * 2 + half;
            float s = 0.f;
            #pragma unroll
            for (int kw = 0; kw < 8; ++kw) s += redf[base + kw * 832];
            gh[g] = s;
        }

        float xr = xps[0 * 256 + b * 16 + uu];
        float xz = xps[1 * 256 + b * 16 + uu];
        float xn = xps[2 * 256 + b * 16 + uu];

        float r = 1.f / (1.f + __expf(-(xr + gh[0] + bh0)));
        float z = 1.f / (1.f + __expf(-(xz + gh[1] + bh1)));
        float nn = tanhf(xn + r * (gh[2] + bh2));
        float hnew = (1.f - z) * nn + z * hprev;
        hprev = hnew;

        hg[((size_t)(t & 1) * 4 + bg) * 8192 + (u0 + uu) * 16 + b] = hnew;
        if (hist) hist[((size_t)t * 64 + b0 + b) * 512 + u0 + uu] = hnew;

        if (pooledp) {
            // 16-lane shuffle reduce over b (threads sharing uu are contiguous lanes)
            float s = hnew;
            s += __shfl_down_sync(0xffffffffu, s, 8, 16);
            s += __shfl_down_sync(0xffffffffu, s, 4, 16);
            s += __shfl_down_sync(0xffffffffu, s, 2, 16);
            s += __shfl_down_sync(0xffffffffu, s, 1, 16);
            if (b == 0)
                pooledp[(size_t)bg * T_ * 512 + t * 512 + u0 + uu] = s;
        }

        if (t < T_ - 1) group_barrier(&epoch, cnt);
    }
}

// ---------------- final FC: combine 4 pooled partials + project ----------------
__global__ void fc_kernel(const float* __restrict__ pooledp, const float* __restrict__ fcW,
                          const float* __restrict__ fcb, float* __restrict__ out)
{
    int t    = blockIdx.x;
    int lane = threadIdx.x;
    float acc[L_];
    #pragma unroll
    for (int l = 0; l < L_; ++l) acc[l] = 0.f;
    for (int k = lane; k < 512; k += 32) {
        float p = pooledp[0 * T_ * 512 + t * 512 + k]
                + pooledp[1 * T_ * 512 + t * 512 + k]
                + pooledp[2 * T_ * 512 + t * 512 + k]
                + pooledp[3 * T_ * 512 + t * 512 + k];
        p *= (1.0f / 64.0f);
        #pragma unroll
        for (int l = 0; l < L_; ++l) acc[l] = fmaf(p, fcW[l * 512 + k], acc[l]);
    }
    #pragma unroll
    for (int l = 0; l < L_; ++l) {
        #pragma unroll
        for (int off = 16; off > 0; off >>= 1)
            acc[l] += __shfl_down_sync(0xffffffffu, acc[l], off);
    }
    if (lane == 0) {
        #pragma unroll
        for (int l = 0; l < L_; ++l) out[t * L_ + l] = acc[l] + fcb[l];
    }
}

// ---------------- launch ----------------
extern "C" void kernel_launch(void* const* d_in, const int* in_sizes, int n_in,
                              void* d_out, int out_size)
{
    const int*   texts = (const int*)  d_in[0];
    const float* emb   = (const float*)d_in[1];
    const float* Wih0  = (const float*)d_in[2];
    const float* Whh0  = (const float*)d_in[3];
    const float* bih0  = (const float*)d_in[4];
    const float* bhh0  = (const float*)d_in[5];
    const float* Wih1  = (const float*)d_in[6];
    const float* Whh1  = (const float*)d_in[7];
    const float* bih1  = (const float*)d_in[8];
    const float* bhh1  = (const float*)d_in[9];
    const float* fcW   = (const float*)d_in[10];
    const float* fcb   = (const float*)d_in[11];
    float* out = (float*)d_out;

    float *xp0, *xp1, *h1, *hT, *pooledp;
    cudaGetSymbolAddress((void**)&xp0,     g_xp0);
    cudaGetSymbolAddress((void**)&xp1,     g_xp1);
    cudaGetSymbolAddress((void**)&h1,      g_h1);
    cudaGetSymbolAddress((void**)&hT,      g_hT);
    cudaGetSymbolAddress((void**)&pooledp, g_pooledp);

    static bool attr_set = false;
    if (!attr_set) {
        cudaFuncSetAttribute(recur_kernel,
                             cudaFuncAttributeMaxDynamicSharedMemorySize, RS_TOTAL);
        attr_set = true;
    }

    const int M = T_ * B_;                  // 32768
    dim3 ggrid(G3H_ / 64, M / 128);         // (24, 256)

    // layer 0 input projection (embedding gather fused)
    gemm_kernel<<<ggrid, 256>>>(emb, texts, Wih0, bih0, xp0, M, G3H_, E_);

    // layer 0 recurrence -> h1 history ([t*B+b][H] for the next GEMM)
    init_kernel<<<1, 128>>>();
    recur_kernel<<<NBLK, NTHR, RS_TOTAL>>>(xp0, Whh0, bhh0, hT, h1, nullptr);

    // layer 1 input projection
    gemm_kernel<<<ggrid, 256>>>(h1, nullptr, Wih1, bih1, xp1, M, G3H_, H_);

    // layer 1 recurrence + partial batch-mean pooling
    init_kernel<<<1, 128>>>();
    recur_kernel<<<NBLK, NTHR, RS_TOTAL>>>(xp1, Whh1, bhh1, hT, nullptr, pooledp);

    // final projection
    fc_kernel<<<T_, 32>>>(pooledp, fcW, fcb, out);
}